// round 1
// baseline (speedup 1.0000x reference)
#include <cuda_runtime.h>
#include <math.h>

#define TTOK   2048      // B*S
#define HDIM   768
#define NEXP   8
#define IDIM   768
#define MAXP   (TTOK*2)  // max pairs per expert (worst case all in one expert)
#define ALPHA  1.702f
#define LIMIT  7.0f

// -------- scratch (static device globals; no dynamic allocation) --------
__device__ int   g_cnt[NEXP];
__device__ int   g_list[NEXP * MAXP];       // slot ids (t*2+k) grouped per expert
__device__ float g_w[TTOK * 2];             // router weight per slot
__device__ float g_act[(size_t)TTOK * 2 * IDIM];   // activated per slot
__device__ float g_down[(size_t)TTOK * 2 * HDIM];  // down output per slot

// ------------------------------ utility ------------------------------
__global__ void zero_cnt_kernel() {
    if (threadIdx.x < NEXP) g_cnt[threadIdx.x] = 0;
}

// ------------------------------ router ------------------------------
// 1 warp per token. logits = x @ Wr + br ; top-2 (stable, lower index wins
// ties, matching jax.lax.top_k) ; softmax over the 2 values ; compact into
// per-expert lists.
__global__ __launch_bounds__(256) void router_kernel(
    const float* __restrict__ x, const float* __restrict__ Wr,
    const float* __restrict__ br)
{
    int warp = threadIdx.x >> 5;
    int lane = threadIdx.x & 31;
    int t = blockIdx.x * 8 + warp;
    if (t >= TTOK) return;

    const float* xr = x + (size_t)t * HDIM;
    float acc[NEXP];
#pragma unroll
    for (int e = 0; e < NEXP; e++) acc[e] = 0.f;

    for (int h = lane; h < HDIM; h += 32) {
        float xv = xr[h];
        const float* w = Wr + h * NEXP;
#pragma unroll
        for (int e = 0; e < NEXP; e++) acc[e] = fmaf(xv, w[e], acc[e]);
    }
#pragma unroll
    for (int e = 0; e < NEXP; e++) {
#pragma unroll
        for (int o = 16; o > 0; o >>= 1)
            acc[e] += __shfl_xor_sync(0xffffffffu, acc[e], o);
    }
    if (lane == 0) {
#pragma unroll
        for (int e = 0; e < NEXP; e++) acc[e] += br[e];

        int i0 = 0; float v0 = acc[0];
#pragma unroll
        for (int e = 1; e < NEXP; e++)
            if (acc[e] > v0) { v0 = acc[e]; i0 = e; }
        int i1 = -1; float v1 = -INFINITY;
#pragma unroll
        for (int e = 0; e < NEXP; e++)
            if (e != i0 && acc[e] > v1) { v1 = acc[e]; i1 = e; }

        float s1 = expf(v1 - v0);
        float d  = 1.f + s1;
        g_w[t * 2 + 0] = 1.f / d;
        g_w[t * 2 + 1] = s1 / d;

        int p0 = atomicAdd(&g_cnt[i0], 1);
        g_list[i0 * MAXP + p0] = t * 2;
        int p1 = atomicAdd(&g_cnt[i1], 1);
        g_list[i1 * MAXP + p1] = t * 2 + 1;
    }
}

// --------------------- stage 1: gate/up GEMM + SwiGLU ---------------------
// Gathered GEMM: act[slot][n] = f(x[tok] . Wgu[e][:, n], x[tok] . Wgu[e][:, I+n])
// Tile: BM=128 slots x BN=64 outputs, BK=16. 256 threads, each 8x4 per plane.
#define BM 128
#define BN 64
#define BK 16

__global__ __launch_bounds__(256) void gu_kernel(
    const float* __restrict__ x, const float* __restrict__ Wgu,
    const float* __restrict__ bgu)
{
    int e   = blockIdx.z;
    int cnt = g_cnt[e];
    int m0  = blockIdx.y * BM;
    if (m0 >= cnt) return;
    int n0  = blockIdx.x * BN;

    __shared__ __align__(16) float sA[BK][BM];
    __shared__ __align__(16) float sBg[BK][BN];
    __shared__ __align__(16) float sBu[BK][BN];
    __shared__ int sSlot[BM];

    int tid = threadIdx.x;
    for (int m = tid; m < BM; m += 256) {
        int idx = m0 + m;
        sSlot[m] = (idx < cnt) ? g_list[e * MAXP + idx] : -1;
    }
    __syncthreads();

    const float* Wg = Wgu + (size_t)e * HDIM * (2 * IDIM);

    int tx = tid & 15;   // col group
    int ty = tid >> 4;   // row group
    float accG[8][4], accU[8][4];
#pragma unroll
    for (int i = 0; i < 8; i++)
#pragma unroll
        for (int j = 0; j < 4; j++) { accG[i][j] = 0.f; accU[i][j] = 0.f; }

    int kb = tid >> 4;          // 0..15 (B k-row)
    int cb = (tid & 15) * 4;    // 0..60 (B col)

    for (int k0 = 0; k0 < HDIM; k0 += BK) {
        // ---- load A (gathered, transposed into sA[k][m]) ----
#pragma unroll
        for (int l = 0; l < 2; l++) {
            int lin = tid + l * 256;       // 0..511
            int kq  = lin >> 7;            // 0..3
            int row = lin & 127;           // 0..127
            int slot = sSlot[row];
            float4 v = make_float4(0.f, 0.f, 0.f, 0.f);
            if (slot >= 0) {
                int tok = slot >> 1;
                v = *(const float4*)&x[(size_t)tok * HDIM + k0 + kq * 4];
            }
            sA[kq * 4 + 0][row] = v.x;
            sA[kq * 4 + 1][row] = v.y;
            sA[kq * 4 + 2][row] = v.z;
            sA[kq * 4 + 3][row] = v.w;
        }
        // ---- load B (gate + up planes) ----
        {
            const float* bp = Wg + (size_t)(k0 + kb) * (2 * IDIM) + n0 + cb;
            float4 vg = *(const float4*)bp;
            float4 vu = *(const float4*)(bp + IDIM);
            *(float4*)&sBg[kb][cb] = vg;
            *(float4*)&sBu[kb][cb] = vu;
        }
        __syncthreads();
#pragma unroll
        for (int kk = 0; kk < BK; kk++) {
            float a[8];
            *(float4*)&a[0] = *(const float4*)&sA[kk][ty * 8];
            *(float4*)&a[4] = *(const float4*)&sA[kk][ty * 8 + 4];
            float bg[4], bu[4];
            *(float4*)&bg[0] = *(const float4*)&sBg[kk][tx * 4];
            *(float4*)&bu[0] = *(const float4*)&sBu[kk][tx * 4];
#pragma unroll
            for (int i = 0; i < 8; i++)
#pragma unroll
                for (int j = 0; j < 4; j++) {
                    accG[i][j] = fmaf(a[i], bg[j], accG[i][j]);
                    accU[i][j] = fmaf(a[i], bu[j], accU[i][j]);
                }
        }
        __syncthreads();
    }

    // ---- epilogue: bias, clamp, SwiGLU, scatter to act scratch ----
    const float* bge = bgu + (size_t)e * 2 * IDIM;
#pragma unroll
    for (int i = 0; i < 8; i++) {
        int m = ty * 8 + i;
        int slot = sSlot[m];
        if (slot < 0) continue;
        float* actRow = g_act + (size_t)slot * IDIM + n0 + tx * 4;
#pragma unroll
        for (int j = 0; j < 4; j++) {
            int n = n0 + tx * 4 + j;
            float g = accG[i][j] + bge[n];
            float u = accU[i][j] + bge[IDIM + n];
            g = fminf(g, LIMIT);
            u = fmaxf(fminf(u, LIMIT), -LIMIT);
            float sig = 1.f / (1.f + expf(-ALPHA * g));
            actRow[j] = (u + 1.f) * (g * sig);
        }
    }
}

// --------------------- stage 2: down GEMM + scale ---------------------
__global__ __launch_bounds__(256) void down_kernel(
    const float* __restrict__ Wd, const float* __restrict__ bd)
{
    int e   = blockIdx.z;
    int cnt = g_cnt[e];
    int m0  = blockIdx.y * BM;
    if (m0 >= cnt) return;
    int n0  = blockIdx.x * BN;

    __shared__ __align__(16) float sA[BK][BM];
    __shared__ __align__(16) float sB[BK][BN];
    __shared__ int sSlot[BM];

    int tid = threadIdx.x;
    for (int m = tid; m < BM; m += 256) {
        int idx = m0 + m;
        sSlot[m] = (idx < cnt) ? g_list[e * MAXP + idx] : -1;
    }
    __syncthreads();

    const float* We = Wd + (size_t)e * IDIM * HDIM;

    int tx = tid & 15;
    int ty = tid >> 4;
    float acc[8][4];
#pragma unroll
    for (int i = 0; i < 8; i++)
#pragma unroll
        for (int j = 0; j < 4; j++) acc[i][j] = 0.f;

    int kb = tid >> 4;
    int cb = (tid & 15) * 4;

    for (int k0 = 0; k0 < IDIM; k0 += BK) {
#pragma unroll
        for (int l = 0; l < 2; l++) {
            int lin = tid + l * 256;
            int kq  = lin >> 7;
            int row = lin & 127;
            int slot = sSlot[row];
            float4 v = make_float4(0.f, 0.f, 0.f, 0.f);
            if (slot >= 0)
                v = *(const float4*)&g_act[(size_t)slot * IDIM + k0 + kq * 4];
            sA[kq * 4 + 0][row] = v.x;
            sA[kq * 4 + 1][row] = v.y;
            sA[kq * 4 + 2][row] = v.z;
            sA[kq * 4 + 3][row] = v.w;
        }
        {
            float4 vb = *(const float4*)&We[(size_t)(k0 + kb) * HDIM + n0 + cb];
            *(float4*)&sB[kb][cb] = vb;
        }
        __syncthreads();
#pragma unroll
        for (int kk = 0; kk < BK; kk++) {
            float a[8];
            *(float4*)&a[0] = *(const float4*)&sA[kk][ty * 8];
            *(float4*)&a[4] = *(const float4*)&sA[kk][ty * 8 + 4];
            float b[4];
            *(float4*)&b[0] = *(const float4*)&sB[kk][tx * 4];
#pragma unroll
            for (int i = 0; i < 8; i++)
#pragma unroll
                for (int j = 0; j < 4; j++)
                    acc[i][j] = fmaf(a[i], b[j], acc[i][j]);
        }
        __syncthreads();
    }

    const float* bde = bd + (size_t)e * HDIM;
#pragma unroll
    for (int i = 0; i < 8; i++) {
        int m = ty * 8 + i;
        int slot = sSlot[m];
        if (slot < 0) continue;
        float w = g_w[slot];
        float* outRow = g_down + (size_t)slot * HDIM + n0 + tx * 4;
#pragma unroll
        for (int j = 0; j < 4; j++) {
            int n = n0 + tx * 4 + j;
            outRow[j] = w * (acc[i][j] + bde[n]);
        }
    }
}

// --------------------------- combine slots ---------------------------
__global__ __launch_bounds__(256) void combine_kernel(float* __restrict__ out)
{
    int idx = blockIdx.x * 256 + threadIdx.x;   // over TTOK*HDIM/4 float4s
    int perTok = HDIM / 4;
    int t = idx / perTok;
    int r = idx - t * perTok;
    const float4* d0 = (const float4*)(g_down + (size_t)(t * 2) * HDIM) + r;
    const float4* d1 = (const float4*)(g_down + (size_t)(t * 2 + 1) * HDIM) + r;
    float4 a = *d0, b = *d1;
    float4 o;
    o.x = a.x + b.x; o.y = a.y + b.y; o.z = a.z + b.z; o.w = a.w + b.w;
    ((float4*)out)[idx] = o;
}

// ------------------------------ launch ------------------------------
extern "C" void kernel_launch(void* const* d_in, const int* in_sizes, int n_in,
                              void* d_out, int out_size)
{
    const float* x   = (const float*)d_in[0];   // (2,1024,768)
    const float* Wr  = (const float*)d_in[1];   // (768,8)
    const float* br  = (const float*)d_in[2];   // (8,)
    const float* Wgu = (const float*)d_in[3];   // (8,768,1536)
    const float* bgu = (const float*)d_in[4];   // (8,1536)
    const float* Wd  = (const float*)d_in[5];   // (8,768,768)
    const float* bd  = (const float*)d_in[6];   // (8,768)
    float* out = (float*)d_out;

    zero_cnt_kernel<<<1, 32>>>();
    router_kernel<<<TTOK / 8, 256>>>(x, Wr, br);

    dim3 ggrid(IDIM / BN, MAXP / BM, NEXP);   // (12, 32, 8)
    gu_kernel<<<ggrid, 256>>>(x, Wgu, bgu);

    dim3 dgrid(HDIM / BN, MAXP / BM, NEXP);   // (12, 32, 8)
    down_kernel<<<dgrid, 256>>>(Wd, bd);

    combine_kernel<<<(TTOK * HDIM / 4) / 256, 256>>>(out);
}

// round 3
// speedup vs baseline: 2.2013x; 2.2013x over previous
#include <cuda_runtime.h>
#include <math.h>
#include <stdint.h>

#define TTOK   2048
#define HDIM   768
#define NEXP   8
#define IDIM   768
#define MAXP   (TTOK*2)
#define ALPHA  1.702f
#define LIMIT  7.0f
#define BK     32
#define NCH    (HDIM / BK)   // 24

// -------- scratch --------
__device__ int   g_cnt[NEXP];
__device__ int   g_list[NEXP * MAXP];
__device__ float g_w[TTOK * 2];
__device__ float g_act[(size_t)TTOK * 2 * IDIM];
__device__ float g_down[(size_t)TTOK * 2 * HDIM];

// ------------------------- helpers -------------------------
__device__ __forceinline__ float to_tf32(float x) {
    uint32_t u;
    asm("cvt.rna.tf32.f32 %0, %1;" : "=r"(u) : "f"(x));
    return __uint_as_float(u);
}
__device__ __forceinline__ float4 cvt4(float4 v) {
    return make_float4(to_tf32(v.x), to_tf32(v.y), to_tf32(v.z), to_tf32(v.w));
}
__device__ __forceinline__ void mma8(float* d, const uint32_t* a, const uint32_t* b) {
    asm volatile(
        "mma.sync.aligned.m16n8k8.row.col.f32.tf32.tf32.f32 "
        "{%0,%1,%2,%3}, {%4,%5,%6,%7}, {%8,%9}, {%0,%1,%2,%3};"
        : "+f"(d[0]), "+f"(d[1]), "+f"(d[2]), "+f"(d[3])
        : "r"(a[0]), "r"(a[1]), "r"(a[2]), "r"(a[3]), "r"(b[0]), "r"(b[1]));
}

// ------------------------------ utility ------------------------------
__global__ void zero_cnt_kernel() {
    if (threadIdx.x < NEXP) g_cnt[threadIdx.x] = 0;
}

// ------------------------------ router ------------------------------
__global__ __launch_bounds__(256) void router_kernel(
    const float* __restrict__ x, const float* __restrict__ Wr,
    const float* __restrict__ br)
{
    int warp = threadIdx.x >> 5;
    int lane = threadIdx.x & 31;
    int t = blockIdx.x * 8 + warp;
    if (t >= TTOK) return;

    const float* xr = x + (size_t)t * HDIM;
    float acc[NEXP];
#pragma unroll
    for (int e = 0; e < NEXP; e++) acc[e] = 0.f;

    for (int h = lane; h < HDIM; h += 32) {
        float xv = xr[h];
        const float* w = Wr + h * NEXP;
#pragma unroll
        for (int e = 0; e < NEXP; e++) acc[e] = fmaf(xv, w[e], acc[e]);
    }
#pragma unroll
    for (int e = 0; e < NEXP; e++) {
#pragma unroll
        for (int o = 16; o > 0; o >>= 1)
            acc[e] += __shfl_xor_sync(0xffffffffu, acc[e], o);
    }
    if (lane == 0) {
#pragma unroll
        for (int e = 0; e < NEXP; e++) acc[e] += br[e];

        int i0 = 0; float v0 = acc[0];
#pragma unroll
        for (int e = 1; e < NEXP; e++)
            if (acc[e] > v0) { v0 = acc[e]; i0 = e; }
        int i1 = -1; float v1 = -INFINITY;
#pragma unroll
        for (int e = 0; e < NEXP; e++)
            if (e != i0 && acc[e] > v1) { v1 = acc[e]; i1 = e; }

        float s1 = expf(v1 - v0);
        float d  = 1.f + s1;
        g_w[t * 2 + 0] = 1.f / d;
        g_w[t * 2 + 1] = s1 / d;

        int p0 = atomicAdd(&g_cnt[i0], 1);
        g_list[i0 * MAXP + p0] = t * 2;
        int p1 = atomicAdd(&g_cnt[i1], 1);
        g_list[i1 * MAXP + p1] = t * 2 + 1;
    }
}

// =============== stage 1: tf32 mma gate/up GEMM + SwiGLU ===============
// Tile: 128 slots x 64 cols (gate plane + up plane), K in 24 chunks of 32.
// 8 warps, 4x2 (M x N), warp tile 32x32 per plane.
__global__ __launch_bounds__(256, 2) void gu_mma(
    const float* __restrict__ x, const float* __restrict__ Wgu,
    const float* __restrict__ bgu)
{
    int e   = blockIdx.z;
    int cnt = g_cnt[e];
    int m0  = blockIdx.y * 128;
    if (m0 >= cnt) return;
    int n0  = blockIdx.x * 64;

    __shared__ __align__(16) float sA [128][36];
    __shared__ __align__(16) float sBg[BK][68];
    __shared__ __align__(16) float sBu[BK][68];
    __shared__ int sSlot[128];

    int tid  = threadIdx.x;
    int wid  = tid >> 5, lane = tid & 31;
    int wM   = wid >> 1, wN = wid & 1;
    int gID  = lane >> 2, tg = lane & 3;

    for (int m = tid; m < 128; m += 256) {
        int idx = m0 + m;
        sSlot[m] = (idx < cnt) ? g_list[e * MAXP + idx] : -1;
    }
    __syncthreads();

    const float* Wg = Wgu + (size_t)e * HDIM * (2 * IDIM);

    // ---- per-thread load mappings ----
    // A: 4 float4 per thread: idx = tid + i*256 ; m = idx>>3 ; kq = idx&7
    const float* aptr[4];
    int mA[4], kqA[4];
#pragma unroll
    for (int i = 0; i < 4; i++) {
        int idx = tid + i * 256;
        mA[i]  = idx >> 3;
        kqA[i] = idx & 7;
        int slot = sSlot[mA[i]];
        aptr[i] = (slot >= 0) ? x + (size_t)(slot >> 1) * HDIM + kqA[i] * 4 : 0;
    }
    // B: 4 float4 per thread (2 per plane): idx2 = tid + (i&1)*256 ;
    // k = idx2>>4 ; n4 = idx2&15 ; plane = i>>1
    const float* bptr[4];
    int kB[4], nB[4];
#pragma unroll
    for (int i = 0; i < 4; i++) {
        int idx2 = tid + (i & 1) * 256;
        kB[i] = idx2 >> 4;
        nB[i] = idx2 & 15;
        int plane = i >> 1;
        bptr[i] = Wg + (size_t)kB[i] * (2 * IDIM) + plane * IDIM + n0 + nB[i] * 4;
    }

    float accG[2][4][4], accU[2][4][4];
#pragma unroll
    for (int mt = 0; mt < 2; mt++)
#pragma unroll
        for (int nt = 0; nt < 4; nt++)
#pragma unroll
            for (int q = 0; q < 4; q++) { accG[mt][nt][q] = 0.f; accU[mt][nt][q] = 0.f; }

    // ---- prefetch chunk 0 ----
    float4 aR[4], bR[4];
#pragma unroll
    for (int i = 0; i < 4; i++)
        aR[i] = aptr[i] ? *(const float4*)aptr[i] : make_float4(0.f, 0.f, 0.f, 0.f);
#pragma unroll
    for (int i = 0; i < 4; i++) bR[i] = *(const float4*)bptr[i];

    for (int c = 0; c < NCH; c++) {
        // store current chunk to smem (tf32-rounded)
#pragma unroll
        for (int i = 0; i < 4; i++)
            *(float4*)&sA[mA[i]][kqA[i] * 4] = cvt4(aR[i]);
#pragma unroll
        for (int i = 0; i < 4; i++) {
            float* dst = (i >> 1) ? &sBu[kB[i]][nB[i] * 4] : &sBg[kB[i]][nB[i] * 4];
            *(float4*)dst = cvt4(bR[i]);
        }
        __syncthreads();

        // prefetch next chunk (overlaps with mma)
        if (c + 1 < NCH) {
            int koff = (c + 1) * BK;
#pragma unroll
            for (int i = 0; i < 4; i++)
                aR[i] = aptr[i] ? *(const float4*)(aptr[i] + koff)
                                : make_float4(0.f, 0.f, 0.f, 0.f);
#pragma unroll
            for (int i = 0; i < 4; i++)
                bR[i] = *(const float4*)(bptr[i] + (size_t)koff * (2 * IDIM));
        }

        // compute 4 k8-steps
#pragma unroll
        for (int k8 = 0; k8 < 4; k8++) {
            int k = k8 * 8;
            uint32_t a[2][4];
#pragma unroll
            for (int mt = 0; mt < 2; mt++) {
                int r0 = wM * 32 + mt * 16 + gID;
                a[mt][0] = __float_as_uint(sA[r0    ][k + tg]);
                a[mt][1] = __float_as_uint(sA[r0 + 8][k + tg]);
                a[mt][2] = __float_as_uint(sA[r0    ][k + tg + 4]);
                a[mt][3] = __float_as_uint(sA[r0 + 8][k + tg + 4]);
            }
#pragma unroll
            for (int nt = 0; nt < 4; nt++) {
                int col = wN * 32 + nt * 8 + gID;
                uint32_t bg[2], bu[2];
                bg[0] = __float_as_uint(sBg[k + tg    ][col]);
                bg[1] = __float_as_uint(sBg[k + tg + 4][col]);
                bu[0] = __float_as_uint(sBu[k + tg    ][col]);
                bu[1] = __float_as_uint(sBu[k + tg + 4][col]);
#pragma unroll
                for (int mt = 0; mt < 2; mt++) {
                    mma8(accG[mt][nt], a[mt], bg);
                    mma8(accU[mt][nt], a[mt], bu);
                }
            }
        }
        __syncthreads();
    }

    // ---- epilogue: bias + clamp + SwiGLU, straight from fragments ----
    const float* bge = bgu + (size_t)e * (2 * IDIM);
#pragma unroll
    for (int mt = 0; mt < 2; mt++) {
#pragma unroll
        for (int half = 0; half < 2; half++) {
            int row = wM * 32 + mt * 16 + half * 8 + gID;
            int slot = sSlot[row];
            if (slot < 0) continue;
            float* outp = g_act + (size_t)slot * IDIM;
#pragma unroll
            for (int nt = 0; nt < 4; nt++) {
                int col = n0 + wN * 32 + nt * 8 + 2 * tg;
                float g0 = accG[mt][nt][half * 2 + 0] + bge[col];
                float g1 = accG[mt][nt][half * 2 + 1] + bge[col + 1];
                float u0 = accU[mt][nt][half * 2 + 0] + bge[IDIM + col];
                float u1 = accU[mt][nt][half * 2 + 1] + bge[IDIM + col + 1];
                g0 = fminf(g0, LIMIT); g1 = fminf(g1, LIMIT);
                u0 = fmaxf(fminf(u0, LIMIT), -LIMIT);
                u1 = fmaxf(fminf(u1, LIMIT), -LIMIT);
                float s0 = 1.f / (1.f + expf(-ALPHA * g0));
                float s1 = 1.f / (1.f + expf(-ALPHA * g1));
                float2 o = make_float2((u0 + 1.f) * (g0 * s0),
                                       (u1 + 1.f) * (g1 * s1));
                *(float2*)(outp + col) = o;
            }
        }
    }
}

// =============== stage 2: tf32 mma down GEMM + scale ===============
__global__ __launch_bounds__(256, 2) void down_mma(
    const float* __restrict__ Wd, const float* __restrict__ bd)
{
    int e   = blockIdx.z;
    int cnt = g_cnt[e];
    int m0  = blockIdx.y * 128;
    if (m0 >= cnt) return;
    int n0  = blockIdx.x * 64;

    __shared__ __align__(16) float sA[128][36];
    __shared__ __align__(16) float sB[BK][68];
    __shared__ int sSlot[128];

    int tid  = threadIdx.x;
    int wid  = tid >> 5, lane = tid & 31;
    int wM   = wid >> 1, wN = wid & 1;
    int gID  = lane >> 2, tg = lane & 3;

    for (int m = tid; m < 128; m += 256) {
        int idx = m0 + m;
        sSlot[m] = (idx < cnt) ? g_list[e * MAXP + idx] : -1;
    }
    __syncthreads();

    const float* We = Wd + (size_t)e * IDIM * HDIM;

    const float* aptr[4];
    int mA[4], kqA[4];
#pragma unroll
    for (int i = 0; i < 4; i++) {
        int idx = tid + i * 256;
        mA[i]  = idx >> 3;
        kqA[i] = idx & 7;
        int slot = sSlot[mA[i]];
        aptr[i] = (slot >= 0) ? g_act + (size_t)slot * IDIM + kqA[i] * 4 : 0;
    }
    const float* bptr[2];
    int kB[2], nB[2];
#pragma unroll
    for (int i = 0; i < 2; i++) {
        int idx2 = tid + i * 256;
        kB[i] = idx2 >> 4;
        nB[i] = idx2 & 15;
        bptr[i] = We + (size_t)kB[i] * HDIM + n0 + nB[i] * 4;
    }

    float acc[2][4][4];
#pragma unroll
    for (int mt = 0; mt < 2; mt++)
#pragma unroll
        for (int nt = 0; nt < 4; nt++)
#pragma unroll
            for (int q = 0; q < 4; q++) acc[mt][nt][q] = 0.f;

    float4 aR[4], bR[2];
#pragma unroll
    for (int i = 0; i < 4; i++)
        aR[i] = aptr[i] ? *(const float4*)aptr[i] : make_float4(0.f, 0.f, 0.f, 0.f);
#pragma unroll
    for (int i = 0; i < 2; i++) bR[i] = *(const float4*)bptr[i];

    for (int c = 0; c < NCH; c++) {
#pragma unroll
        for (int i = 0; i < 4; i++)
            *(float4*)&sA[mA[i]][kqA[i] * 4] = cvt4(aR[i]);
#pragma unroll
        for (int i = 0; i < 2; i++)
            *(float4*)&sB[kB[i]][nB[i] * 4] = cvt4(bR[i]);
        __syncthreads();

        if (c + 1 < NCH) {
            int koff = (c + 1) * BK;
#pragma unroll
            for (int i = 0; i < 4; i++)
                aR[i] = aptr[i] ? *(const float4*)(aptr[i] + koff)
                                : make_float4(0.f, 0.f, 0.f, 0.f);
#pragma unroll
            for (int i = 0; i < 2; i++)
                bR[i] = *(const float4*)(bptr[i] + (size_t)koff * HDIM);
        }

#pragma unroll
        for (int k8 = 0; k8 < 4; k8++) {
            int k = k8 * 8;
            uint32_t a[2][4];
#pragma unroll
            for (int mt = 0; mt < 2; mt++) {
                int r0 = wM * 32 + mt * 16 + gID;
                a[mt][0] = __float_as_uint(sA[r0    ][k + tg]);
                a[mt][1] = __float_as_uint(sA[r0 + 8][k + tg]);
                a[mt][2] = __float_as_uint(sA[r0    ][k + tg + 4]);
                a[mt][3] = __float_as_uint(sA[r0 + 8][k + tg + 4]);
            }
#pragma unroll
            for (int nt = 0; nt < 4; nt++) {
                int col = wN * 32 + nt * 8 + gID;
                uint32_t b[2];
                b[0] = __float_as_uint(sB[k + tg    ][col]);
                b[1] = __float_as_uint(sB[k + tg + 4][col]);
#pragma unroll
                for (int mt = 0; mt < 2; mt++)
                    mma8(acc[mt][nt], a[mt], b);
            }
        }
        __syncthreads();
    }

    const float* bde = bd + (size_t)e * HDIM;
#pragma unroll
    for (int mt = 0; mt < 2; mt++) {
#pragma unroll
        for (int half = 0; half < 2; half++) {
            int row = wM * 32 + mt * 16 + half * 8 + gID;
            int slot = sSlot[row];
            if (slot < 0) continue;
            float w = g_w[slot];
            float* outp = g_down + (size_t)slot * HDIM;
#pragma unroll
            for (int nt = 0; nt < 4; nt++) {
                int col = n0 + wN * 32 + nt * 8 + 2 * tg;
                float2 o = make_float2(
                    w * (acc[mt][nt][half * 2 + 0] + bde[col]),
                    w * (acc[mt][nt][half * 2 + 1] + bde[col + 1]));
                *(float2*)(outp + col) = o;
            }
        }
    }
}

// --------------------------- combine slots ---------------------------
__global__ __launch_bounds__(256) void combine_kernel(float* __restrict__ out)
{
    int idx = blockIdx.x * 256 + threadIdx.x;
    int perTok = HDIM / 4;
    int t = idx / perTok;
    int r = idx - t * perTok;
    const float4* d0 = (const float4*)(g_down + (size_t)(t * 2) * HDIM) + r;
    const float4* d1 = (const float4*)(g_down + (size_t)(t * 2 + 1) * HDIM) + r;
    float4 a = *d0, b = *d1;
    float4 o;
    o.x = a.x + b.x; o.y = a.y + b.y; o.z = a.z + b.z; o.w = a.w + b.w;
    ((float4*)out)[idx] = o;
}

// ------------------------------ launch ------------------------------
extern "C" void kernel_launch(void* const* d_in, const int* in_sizes, int n_in,
                              void* d_out, int out_size)
{
    const float* x   = (const float*)d_in[0];
    const float* Wr  = (const float*)d_in[1];
    const float* br  = (const float*)d_in[2];
    const float* Wgu = (const float*)d_in[3];
    const float* bgu = (const float*)d_in[4];
    const float* Wd  = (const float*)d_in[5];
    const float* bd  = (const float*)d_in[6];
    float* out = (float*)d_out;

    zero_cnt_kernel<<<1, 32>>>();
    router_kernel<<<TTOK / 8, 256>>>(x, Wr, br);

    dim3 ggrid(IDIM / 64, MAXP / 128, NEXP);   // (12, 32, 8)
    gu_mma<<<ggrid, 256>>>(x, Wgu, bgu);

    dim3 dgrid(HDIM / 64, MAXP / 128, NEXP);   // (12, 32, 8)
    down_mma<<<dgrid, 256>>>(Wd, bd);

    combine_kernel<<<(TTOK * HDIM / 4) / 256, 256>>>(out);
}

// round 4
// speedup vs baseline: 3.2302x; 1.4674x over previous
#include <cuda_runtime.h>
#include <math.h>
#include <stdint.h>

#define TTOK   2048
#define HDIM   768
#define NEXP   8
#define IDIM   768
#define MAXP   (TTOK*2)
#define ALPHA  1.702f
#define LIMIT  7.0f
#define BK     32
#define NCH    (HDIM / BK)   // 24

// -------- scratch --------
__device__ int   g_cnt[NEXP];
__device__ int   g_list[NEXP * MAXP];
__device__ float g_w[TTOK * 2];
__device__ float g_act[(size_t)TTOK * 2 * IDIM];   // stored tf32-rounded

// ------------------------- helpers -------------------------
__device__ __forceinline__ uint32_t tf32u(float x) {
    uint32_t u;
    asm("cvt.rna.tf32.f32 %0, %1;" : "=r"(u) : "f"(x));
    return u;
}
__device__ __forceinline__ float to_tf32f(float x) {
    return __uint_as_float(tf32u(x));
}
__device__ __forceinline__ void mma8(float* d, const uint32_t* a, const uint32_t* b) {
    asm volatile(
        "mma.sync.aligned.m16n8k8.row.col.f32.tf32.tf32.f32 "
        "{%0,%1,%2,%3}, {%4,%5,%6,%7}, {%8,%9}, {%0,%1,%2,%3};"
        : "+f"(d[0]), "+f"(d[1]), "+f"(d[2]), "+f"(d[3])
        : "r"(a[0]), "r"(a[1]), "r"(a[2]), "r"(a[3]), "r"(b[0]), "r"(b[1]));
}
__device__ __forceinline__ uint32_t smem_u32(const void* p) {
    uint32_t a;
    asm("{ .reg .u64 t; cvta.to.shared.u64 t, %1; cvt.u32.u64 %0, t; }"
        : "=r"(a) : "l"(p));
    return a;
}
__device__ __forceinline__ void cp16(uint32_t dst, const void* src, int sz) {
    asm volatile("cp.async.cg.shared.global [%0], [%1], 16, %2;"
                 :: "r"(dst), "l"(src), "r"(sz));
}
#define CP_COMMIT() asm volatile("cp.async.commit_group;" ::: "memory")
#define CP_WAIT(n)  asm volatile("cp.async.wait_group %0;" :: "n"(n) : "memory")

// A tile: 128 x 32 fp32, row stride 36 (bank-distinct: gID*4+tg)
// B tile:  32 x 64 fp32, row stride 72 (bank-distinct: tg*8+gID)
#define A_STRIDE 36
#define B_STRIDE 72
#define A_BYTES  (128 * A_STRIDE * 4)    // 18432
#define B_BYTES  (BK * B_STRIDE * 4)     // 9216

// ------------------------------ init ------------------------------
__global__ __launch_bounds__(256) void init_kernel(float* __restrict__ out)
{
    int idx = blockIdx.x * 256 + threadIdx.x;
    if (idx < NEXP) g_cnt[idx] = 0;
    if (idx < TTOK * HDIM / 4)
        ((float4*)out)[idx] = make_float4(0.f, 0.f, 0.f, 0.f);
}

// ------------------------------ router ------------------------------
__global__ __launch_bounds__(256) void router_kernel(
    const float* __restrict__ x, const float* __restrict__ Wr,
    const float* __restrict__ br)
{
    int warp = threadIdx.x >> 5;
    int lane = threadIdx.x & 31;
    int t = blockIdx.x * 8 + warp;
    if (t >= TTOK) return;

    const float* xr = x + (size_t)t * HDIM;
    float acc[NEXP];
#pragma unroll
    for (int e = 0; e < NEXP; e++) acc[e] = 0.f;

    for (int h = lane; h < HDIM; h += 32) {
        float xv = xr[h];
        const float* w = Wr + h * NEXP;
#pragma unroll
        for (int e = 0; e < NEXP; e++) acc[e] = fmaf(xv, w[e], acc[e]);
    }
#pragma unroll
    for (int e = 0; e < NEXP; e++) {
#pragma unroll
        for (int o = 16; o > 0; o >>= 1)
            acc[e] += __shfl_xor_sync(0xffffffffu, acc[e], o);
    }
    if (lane == 0) {
#pragma unroll
        for (int e = 0; e < NEXP; e++) acc[e] += br[e];

        int i0 = 0; float v0 = acc[0];
#pragma unroll
        for (int e = 1; e < NEXP; e++)
            if (acc[e] > v0) { v0 = acc[e]; i0 = e; }
        int i1 = -1; float v1 = -INFINITY;
#pragma unroll
        for (int e = 0; e < NEXP; e++)
            if (e != i0 && acc[e] > v1) { v1 = acc[e]; i1 = e; }

        float s1 = expf(v1 - v0);
        float d  = 1.f + s1;
        g_w[t * 2 + 0] = 1.f / d;
        g_w[t * 2 + 1] = s1 / d;

        int p0 = atomicAdd(&g_cnt[i0], 1);
        g_list[i0 * MAXP + p0] = t * 2;
        int p1 = atomicAdd(&g_cnt[i1], 1);
        g_list[i1 * MAXP + p1] = t * 2 + 1;
    }
}

// =============== stage 1: tf32 mma gate/up GEMM + SwiGLU ===============
// 128 slots x 64 cols per plane, K in 24 chunks of 32, 3-stage cp.async.
// Stage layout: A (18432) | Bg (9216) | Bu (9216)  = 36864 x 3 stages.
#define GU_STAGE (A_BYTES + 2 * B_BYTES)   // 36864

__global__ __launch_bounds__(256, 2) void gu_mma(
    const float* __restrict__ x, const float* __restrict__ Wgu,
    const float* __restrict__ bgu)
{
    int e   = blockIdx.z;
    int cnt = g_cnt[e];
    int m0  = blockIdx.y * 128;
    if (m0 >= cnt) return;
    int n0  = blockIdx.x * 64;

    extern __shared__ __align__(16) char dsm[];
    __shared__ int sSlot[128];

    int tid  = threadIdx.x;
    int wid  = tid >> 5, lane = tid & 31;
    int wM   = wid >> 1, wN = wid & 1;
    int gID  = lane >> 2, tg = lane & 3;

    for (int m = tid; m < 128; m += 256) {
        int idx = m0 + m;
        sSlot[m] = (idx < cnt) ? g_list[e * MAXP + idx] : -1;
    }
    __syncthreads();

    const float* Wg = Wgu + (size_t)e * HDIM * (2 * IDIM);
    uint32_t smb = smem_u32(dsm);

    // per-thread copy mappings
    const float* aSrc[4]; int aSz[4]; uint32_t aDst[4];
#pragma unroll
    for (int i = 0; i < 4; i++) {
        int idx = tid + i * 256;
        int m = idx >> 3, kq = idx & 7;
        int slot = sSlot[m];
        aSrc[i] = (slot >= 0) ? x + (size_t)(slot >> 1) * HDIM + kq * 4 : x;
        aSz[i]  = (slot >= 0) ? 16 : 0;
        aDst[i] = (uint32_t)(m * A_STRIDE + kq * 4) * 4u;
    }
    const float* bSrc[2]; uint32_t bDst[2];
#pragma unroll
    for (int i = 0; i < 2; i++) {
        int idx = tid + i * 256;
        int k = idx >> 4, n4 = idx & 15;
        bSrc[i] = Wg + (size_t)k * (2 * IDIM) + n0 + n4 * 4;
        bDst[i] = (uint32_t)(k * B_STRIDE + n4 * 4) * 4u;
    }

    float accG[2][4][4], accU[2][4][4];
#pragma unroll
    for (int mt = 0; mt < 2; mt++)
#pragma unroll
        for (int nt = 0; nt < 4; nt++)
#pragma unroll
            for (int q = 0; q < 4; q++) { accG[mt][nt][q] = 0.f; accU[mt][nt][q] = 0.f; }

#define GU_ISSUE(c) do {                                                       \
    uint32_t st = smb + (uint32_t)((c) % 3) * GU_STAGE;                        \
    int k0 = (c) * BK;                                                         \
    _Pragma("unroll")                                                          \
    for (int i = 0; i < 4; i++) cp16(st + aDst[i], aSrc[i] + k0, aSz[i]);      \
    _Pragma("unroll")                                                          \
    for (int i = 0; i < 2; i++) {                                              \
        const float* bp = bSrc[i] + (size_t)k0 * (2 * IDIM);                   \
        cp16(st + A_BYTES + bDst[i],           bp,        16);                 \
        cp16(st + A_BYTES + B_BYTES + bDst[i], bp + IDIM, 16);                 \
    } } while (0)

    GU_ISSUE(0); CP_COMMIT();
    GU_ISSUE(1); CP_COMMIT();

    for (int c = 0; c < NCH; c++) {
        CP_WAIT(1);
        __syncthreads();
        const float* fA  = (const float*)(dsm + (c % 3) * GU_STAGE);
        const float* fBg = (const float*)(dsm + (c % 3) * GU_STAGE + A_BYTES);
        const float* fBu = (const float*)(dsm + (c % 3) * GU_STAGE + A_BYTES + B_BYTES);

#pragma unroll
        for (int k8 = 0; k8 < 4; k8++) {
            int k = k8 * 8;
            uint32_t a[2][4];
#pragma unroll
            for (int mt = 0; mt < 2; mt++) {
                int r0 = wM * 32 + mt * 16 + gID;
                a[mt][0] = tf32u(fA[r0 * A_STRIDE + k + tg]);
                a[mt][1] = tf32u(fA[(r0 + 8) * A_STRIDE + k + tg]);
                a[mt][2] = tf32u(fA[r0 * A_STRIDE + k + tg + 4]);
                a[mt][3] = tf32u(fA[(r0 + 8) * A_STRIDE + k + tg + 4]);
            }
#pragma unroll
            for (int nt = 0; nt < 4; nt++) {
                int col = wN * 32 + nt * 8 + gID;
                uint32_t bg[2], bu[2];
                bg[0] = tf32u(fBg[(k + tg) * B_STRIDE + col]);
                bg[1] = tf32u(fBg[(k + tg + 4) * B_STRIDE + col]);
                bu[0] = tf32u(fBu[(k + tg) * B_STRIDE + col]);
                bu[1] = tf32u(fBu[(k + tg + 4) * B_STRIDE + col]);
#pragma unroll
                for (int mt = 0; mt < 2; mt++) {
                    mma8(accG[mt][nt], a[mt], bg);
                    mma8(accU[mt][nt], a[mt], bu);
                }
            }
        }
        __syncthreads();
        if (c + 2 < NCH) GU_ISSUE(c + 2);
        CP_COMMIT();
    }

    // ---- epilogue: bias + clamp + SwiGLU, tf32-rounded store to g_act ----
    const float* bge = bgu + (size_t)e * (2 * IDIM);
#pragma unroll
    for (int mt = 0; mt < 2; mt++) {
#pragma unroll
        for (int half = 0; half < 2; half++) {
            int row = wM * 32 + mt * 16 + half * 8 + gID;
            int slot = sSlot[row];
            if (slot < 0) continue;
            float* outp = g_act + (size_t)slot * IDIM;
#pragma unroll
            for (int nt = 0; nt < 4; nt++) {
                int col = n0 + wN * 32 + nt * 8 + 2 * tg;
                float g0 = accG[mt][nt][half * 2 + 0] + bge[col];
                float g1 = accG[mt][nt][half * 2 + 1] + bge[col + 1];
                float u0 = accU[mt][nt][half * 2 + 0] + bge[IDIM + col];
                float u1 = accU[mt][nt][half * 2 + 1] + bge[IDIM + col + 1];
                g0 = fminf(g0, LIMIT); g1 = fminf(g1, LIMIT);
                u0 = fmaxf(fminf(u0, LIMIT), -LIMIT);
                u1 = fmaxf(fminf(u1, LIMIT), -LIMIT);
                float s0 = 1.f / (1.f + expf(-ALPHA * g0));
                float s1 = 1.f / (1.f + expf(-ALPHA * g1));
                float2 o = make_float2(to_tf32f((u0 + 1.f) * (g0 * s0)),
                                       to_tf32f((u1 + 1.f) * (g1 * s1)));
                *(float2*)(outp + col) = o;
            }
        }
    }
}

// =============== stage 2: tf32 mma down GEMM + weighted atomic combine ===============
#define DN_STAGE (A_BYTES + B_BYTES)   // 27648

__global__ __launch_bounds__(256, 2) void down_mma(
    const float* __restrict__ Wd, const float* __restrict__ bd,
    float* __restrict__ out)
{
    int e   = blockIdx.z;
    int cnt = g_cnt[e];
    int m0  = blockIdx.y * 128;
    if (m0 >= cnt) return;
    int n0  = blockIdx.x * 64;

    extern __shared__ __align__(16) char dsm[];
    __shared__ int sSlot[128];

    int tid  = threadIdx.x;
    int wid  = tid >> 5, lane = tid & 31;
    int wM   = wid >> 1, wN = wid & 1;
    int gID  = lane >> 2, tg = lane & 3;

    for (int m = tid; m < 128; m += 256) {
        int idx = m0 + m;
        sSlot[m] = (idx < cnt) ? g_list[e * MAXP + idx] : -1;
    }
    __syncthreads();

    const float* We = Wd + (size_t)e * IDIM * HDIM;
    uint32_t smb = smem_u32(dsm);

    const float* aSrc[4]; int aSz[4]; uint32_t aDst[4];
#pragma unroll
    for (int i = 0; i < 4; i++) {
        int idx = tid + i * 256;
        int m = idx >> 3, kq = idx & 7;
        int slot = sSlot[m];
        aSrc[i] = (slot >= 0) ? g_act + (size_t)slot * IDIM + kq * 4 : g_act;
        aSz[i]  = (slot >= 0) ? 16 : 0;
        aDst[i] = (uint32_t)(m * A_STRIDE + kq * 4) * 4u;
    }
    const float* bSrc[2]; uint32_t bDst[2];
#pragma unroll
    for (int i = 0; i < 2; i++) {
        int idx = tid + i * 256;
        int k = idx >> 4, n4 = idx & 15;
        bSrc[i] = We + (size_t)k * HDIM + n0 + n4 * 4;
        bDst[i] = (uint32_t)(k * B_STRIDE + n4 * 4) * 4u;
    }

    float acc[2][4][4];
#pragma unroll
    for (int mt = 0; mt < 2; mt++)
#pragma unroll
        for (int nt = 0; nt < 4; nt++)
#pragma unroll
            for (int q = 0; q < 4; q++) acc[mt][nt][q] = 0.f;

#define DN_ISSUE(c) do {                                                       \
    uint32_t st = smb + (uint32_t)((c) % 3) * DN_STAGE;                        \
    int k0 = (c) * BK;                                                         \
    _Pragma("unroll")                                                          \
    for (int i = 0; i < 4; i++) cp16(st + aDst[i], aSrc[i] + k0, aSz[i]);      \
    _Pragma("unroll")                                                          \
    for (int i = 0; i < 2; i++)                                                \
        cp16(st + A_BYTES + bDst[i], bSrc[i] + (size_t)k0 * HDIM, 16);         \
    } while (0)

    DN_ISSUE(0); CP_COMMIT();
    DN_ISSUE(1); CP_COMMIT();

    for (int c = 0; c < NCH; c++) {
        CP_WAIT(1);
        __syncthreads();
        const float* fA = (const float*)(dsm + (c % 3) * DN_STAGE);
        const float* fB = (const float*)(dsm + (c % 3) * DN_STAGE + A_BYTES);

#pragma unroll
        for (int k8 = 0; k8 < 4; k8++) {
            int k = k8 * 8;
            uint32_t a[2][4];
#pragma unroll
            for (int mt = 0; mt < 2; mt++) {
                int r0 = wM * 32 + mt * 16 + gID;
                // g_act already tf32-rounded: no cvt needed
                a[mt][0] = __float_as_uint(fA[r0 * A_STRIDE + k + tg]);
                a[mt][1] = __float_as_uint(fA[(r0 + 8) * A_STRIDE + k + tg]);
                a[mt][2] = __float_as_uint(fA[r0 * A_STRIDE + k + tg + 4]);
                a[mt][3] = __float_as_uint(fA[(r0 + 8) * A_STRIDE + k + tg + 4]);
            }
#pragma unroll
            for (int nt = 0; nt < 4; nt++) {
                int col = wN * 32 + nt * 8 + gID;
                uint32_t b[2];
                b[0] = tf32u(fB[(k + tg) * B_STRIDE + col]);
                b[1] = tf32u(fB[(k + tg + 4) * B_STRIDE + col]);
#pragma unroll
                for (int mt = 0; mt < 2; mt++)
                    mma8(acc[mt][nt], a[mt], b);
            }
        }
        __syncthreads();
        if (c + 2 < NCH) DN_ISSUE(c + 2);
        CP_COMMIT();
    }

    // ---- epilogue: weighted atomic accumulate into out ----
    const float* bde = bd + (size_t)e * HDIM;
#pragma unroll
    for (int mt = 0; mt < 2; mt++) {
#pragma unroll
        for (int half = 0; half < 2; half++) {
            int row = wM * 32 + mt * 16 + half * 8 + gID;
            int slot = sSlot[row];
            if (slot < 0) continue;
            float w = g_w[slot];
            float* outp = out + (size_t)(slot >> 1) * HDIM;
#pragma unroll
            for (int nt = 0; nt < 4; nt++) {
                int col = n0 + wN * 32 + nt * 8 + 2 * tg;
                atomicAdd(outp + col,     w * (acc[mt][nt][half * 2 + 0] + bde[col]));
                atomicAdd(outp + col + 1, w * (acc[mt][nt][half * 2 + 1] + bde[col + 1]));
            }
        }
    }
}

// ------------------------------ launch ------------------------------
extern "C" void kernel_launch(void* const* d_in, const int* in_sizes, int n_in,
                              void* d_out, int out_size)
{
    const float* x   = (const float*)d_in[0];
    const float* Wr  = (const float*)d_in[1];
    const float* br  = (const float*)d_in[2];
    const float* Wgu = (const float*)d_in[3];
    const float* bgu = (const float*)d_in[4];
    const float* Wd  = (const float*)d_in[5];
    const float* bd  = (const float*)d_in[6];
    float* out = (float*)d_out;

    const int GU_SMEM = 3 * GU_STAGE;   // 110592
    const int DN_SMEM = 3 * DN_STAGE;   // 82944
    cudaFuncSetAttribute(gu_mma,   cudaFuncAttributeMaxDynamicSharedMemorySize, GU_SMEM);
    cudaFuncSetAttribute(down_mma, cudaFuncAttributeMaxDynamicSharedMemorySize, DN_SMEM);

    init_kernel<<<(TTOK * HDIM / 4 + 255) / 256, 256>>>(out);
    router_kernel<<<TTOK / 8, 256>>>(x, Wr, br);

    dim3 ggrid(IDIM / 64, MAXP / 128, NEXP);   // (12, 32, 8)
    gu_mma<<<ggrid, 256, GU_SMEM>>>(x, Wgu, bgu);

    dim3 dgrid(HDIM / 64, MAXP / 128, NEXP);   // (12, 32, 8)
    down_mma<<<dgrid, 256, DN_SMEM>>>(Wd, bd, out);
}